// round 4
// baseline (speedup 1.0000x reference)
#include <cuda_runtime.h>
#include <cuda_bf16.h>
#include <cstdint>

#define M_CONST   100
#define GROUPS    25      // M/4 float4 groups per row
#define ROWS_ITER 10      // rows per block iteration (250 active threads)
#define ACTIVE    (GROUPS * ROWS_ITER)

// ---- packed f32x2 helpers (sm_103a) ----
__device__ __forceinline__ uint64_t pk2(float lo, float hi) {
    uint64_t r; asm("mov.b64 %0, {%1,%2};" : "=l"(r) : "f"(lo), "f"(hi)); return r;
}
__device__ __forceinline__ void upk2(uint64_t v, float& lo, float& hi) {
    asm("mov.b64 {%0,%1}, %2;" : "=f"(lo), "=f"(hi) : "l"(v));
}
__device__ __forceinline__ uint64_t fma2_(uint64_t a, uint64_t b, uint64_t c) {
    uint64_t d; asm("fma.rn.f32x2 %0,%1,%2,%3;" : "=l"(d) : "l"(a), "l"(b), "l"(c)); return d;
}
__device__ __forceinline__ uint64_t add2_(uint64_t a, uint64_t b) {
    uint64_t d; asm("add.rn.f32x2 %0,%1,%2;" : "=l"(d) : "l"(a), "l"(b)); return d;
}
__device__ __forceinline__ uint64_t mul2_(uint64_t a, uint64_t b) {
    uint64_t d; asm("mul.rn.f32x2 %0,%1,%2;" : "=l"(d) : "l"(a), "l"(b)); return d;
}
__device__ __forceinline__ uint64_t neg2_(uint64_t a) {   // sign flip, ALU pipe
    return a ^ 0x8000000080000000ULL;
}
__device__ __forceinline__ float ex2_(float x) {
    float r; asm("ex2.approx.f32 %0, %1;" : "=f"(r) : "f"(x)); return r;
}
__device__ __forceinline__ float rcp_(float x) {
    float r; asm("rcp.approx.f32 %0, %1;" : "=f"(r) : "f"(x)); return r;
}

#define NEG_HALF_LOG2E -0.7213475204444817f  // -0.5*log2(e), folds exp->ex2
#define INV_TWO_PI      0.15915494309189535f

__global__ __launch_bounds__(256) void ContinuousSoftmax_kernel(
    const float* __restrict__ theta,        // [N,6]
    const float* __restrict__ basis_mu,     // [M,2]
    const float* __restrict__ basis_sigma,  // [M,2,2] symmetric
    float* __restrict__ out,                // [N,M]
    int N)
{
    const int tid = threadIdx.x;
    if (tid >= ACTIVE) return;
    const int r_local = tid / GROUPS;
    const int g       = tid - r_local * GROUPS;   // 0..24

    // ---- one-time: cache this thread's 4 basis entries as f32x2 pairs ----
    const float4* bm = reinterpret_cast<const float4*>(basis_mu) + 2 * g;
    const float4  m01 = bm[0];
    const float4  m23 = bm[1];
    const float4* bs = reinterpret_cast<const float4*>(basis_sigma) + 4 * g;
    const float4  sg0 = bs[0], sg1 = bs[1], sg2 = bs[2], sg3 = bs[3];

    uint64_t nbm0[2], nbm1[2], b00[2], b01[2], b11[2];
    nbm0[0] = pk2(-m01.x, -m01.z);  nbm0[1] = pk2(-m23.x, -m23.z);
    nbm1[0] = pk2(-m01.y, -m01.w);  nbm1[1] = pk2(-m23.y, -m23.w);
    b00[0]  = pk2(sg0.x, sg1.x);    b00[1]  = pk2(sg2.x, sg3.x);
    b01[0]  = pk2(sg0.y, sg1.y);    b01[1]  = pk2(sg2.y, sg3.y);
    b11[0]  = pk2(sg0.w, sg1.w);    b11[1]  = pk2(sg2.w, sg3.w);

    const uint64_t cArg = pk2(NEG_HALF_LOG2E, NEG_HALF_LOG2E);
    const uint64_t cItp = pk2(INV_TWO_PI, INV_TWO_PI);

    const int stride = gridDim.x * ROWS_ITER;
    const float2* th2 = reinterpret_cast<const float2*>(theta);

    int n = blockIdx.x * ROWS_ITER + r_local;
    if (n >= N) return;

    // ---- software pipeline: preload theta for the first row ----
    float2 e  = th2[(size_t)n * 3 + 0];
    float2 q0 = th2[(size_t)n * 3 + 1];
    float2 q1 = th2[(size_t)n * 3 + 2];

    while (true) {
        const int n_next = n + stride;
        // Prefetch next row's theta NOW (clamped: always a valid address).
        const size_t pidx = (size_t)(n_next < N ? n_next : n) * 3;
        const float2 en  = th2[pidx + 0];
        const float2 q0n = th2[pidx + 1];
        const float2 q1n = th2[pidx + 2];

        // ---- setup: overlap products with the MUFU.RCP latency ----
        const float d    = q0.x * q1.y - q0.y * q1.x;
        const float r    = rcp_(d);                       // in flight...
        const float u01  = -0.5f * (q0.y + q1.x);         // ...meanwhile:
        const float m0p  = q1.y * e.x + u01 * e.y;        // unscaled mu * (-2d)
        const float m1p  = u01 * e.x + q0.x * e.y;
        const float inv  = -0.5f * r;                     // = -1/(2d)
        const float s00  = q1.y * inv;
        const float s11  = q0.x * inv;
        const float s01  = u01  * inv;
        const float inv2 = inv * inv;                     // mu = m' * inv ... but
        // mu must equal s·eta exactly as computed from s; m' * inv reproduces it:
        const float mu0  = m0p * inv;
        const float mu1  = m1p * inv;
        (void)inv2;

        const uint64_t s00v = pk2(s00, s00);
        const uint64_t s01v = pk2(s01, s01);
        const uint64_t s11v = pk2(s11, s11);
        const uint64_t mu0v = pk2(mu0, mu0);
        const uint64_t mu1v = pk2(mu1, mu1);

        float res[4];
        #pragma unroll
        for (int p = 0; p < 2; ++p) {
            const uint64_t c00  = add2_(s00v, b00[p]);
            const uint64_t c01  = add2_(s01v, b01[p]);
            const uint64_t c11  = add2_(s11v, b11[p]);
            const uint64_t dx   = add2_(mu0v, nbm0[p]);
            const uint64_t dy   = add2_(mu1v, nbm1[p]);
            const uint64_t nc01 = neg2_(c01);
            const uint64_t det  = fma2_(nc01, c01, mul2_(c00, c11));
            const uint64_t xx   = mul2_(dx, dx);
            const uint64_t yy   = mul2_(dy, dy);
            const uint64_t dxy  = mul2_(dx, dy);
            const uint64_t dxy2 = add2_(dxy, dxy);
            uint64_t num = mul2_(c11, xx);
            num = fma2_(c00, yy, num);
            num = fma2_(nc01, dxy2, num);

            float d0, d1; upk2(det, d0, d1);
            const float r0 = rsqrtf(d0);
            const float r1 = rsqrtf(d1);
            const uint64_t rsv  = pk2(r0, r1);
            const uint64_t idet = mul2_(rsv, rsv);
            const uint64_t argv = mul2_(mul2_(num, idet), cArg);
            float a0, a1; upk2(argv, a0, a1);
            const float e0 = ex2_(a0);
            const float e1 = ex2_(a1);
            const uint64_t scl = mul2_(rsv, cItp);
            const uint64_t rv  = mul2_(pk2(e0, e1), scl);
            upk2(rv, res[2 * p], res[2 * p + 1]);
        }
        float4 v = make_float4(res[0], res[1], res[2], res[3]);
        *reinterpret_cast<float4*>(out + (size_t)n * M_CONST + 4 * g) = v;

        if (n_next >= N) break;
        n = n_next;
        e = en; q0 = q0n; q1 = q1n;
    }
}

extern "C" void kernel_launch(void* const* d_in, const int* in_sizes, int n_in,
                              void* d_out, int out_size) {
    const float* theta       = (const float*)d_in[0];
    const float* basis_mu    = (const float*)d_in[1];
    const float* basis_sigma = (const float*)d_in[2];
    float* out = (float*)d_out;

    const int N = in_sizes[0] / 6;

    const int threads = 256;
    const int needed  = (N + ROWS_ITER - 1) / ROWS_ITER;
    int blocks = 1536;
    if (blocks > needed) blocks = needed;
    ContinuousSoftmax_kernel<<<blocks, threads>>>(theta, basis_mu, basis_sigma,
                                                  out, N);
}